// round 14
// baseline (speedup 1.0000x reference)
#include <cuda_runtime.h>
#include <cuda_fp16.h>
#include <math.h>
#include <stdint.h>

#define B_ 2
#define T_ 2048
#define C_ 1024
#define H_ 16
#define D_ 64
#define CC_ (C_*C_)

// Scratch (allocation-free rule: __device__ globals)
__device__ __half g_xh[(size_t)B_*T_*C_];      // fp16 activations (x, then attn out)
__device__ __half g_wh[(size_t)4*CC_];         // fp16 weights: Wq,Wk,Wv,Wo
__device__ __half g_qh[(size_t)B_*H_*T_*D_];
__device__ __half g_kh[(size_t)B_*H_*T_*D_];
__device__ __half g_vh[(size_t)B_*H_*T_*D_];
__device__ float2 g_rope[(size_t)T_*32];       // (cos, sin) per (t, d)

#define QSCALE 0.18033688011112042f   // 0.125 * log2(e)

// ---------------------------------------------------------------------------
// common helpers
// ---------------------------------------------------------------------------
__device__ __forceinline__ void cp_async16(uint32_t dst, const void* src) {
    asm volatile("cp.async.ca.shared.global [%0], [%1], 16;" :: "r"(dst), "l"(src));
}
__device__ __forceinline__ void ldmatrix_x4(uint32_t& r0, uint32_t& r1,
                                            uint32_t& r2, uint32_t& r3, uint32_t a) {
    asm volatile("ldmatrix.sync.aligned.m8n8.x4.shared.b16 {%0,%1,%2,%3}, [%4];"
                 : "=r"(r0), "=r"(r1), "=r"(r2), "=r"(r3) : "r"(a));
}
__device__ __forceinline__ void ldmatrix_x4_t(uint32_t& r0, uint32_t& r1,
                                              uint32_t& r2, uint32_t& r3, uint32_t a) {
    asm volatile("ldmatrix.sync.aligned.m8n8.x4.trans.shared.b16 {%0,%1,%2,%3}, [%4];"
                 : "=r"(r0), "=r"(r1), "=r"(r2), "=r"(r3) : "r"(a));
}
__device__ __forceinline__ void mma16816(float* d, const uint32_t* a, const uint32_t* b) {
    asm volatile("mma.sync.aligned.m16n8k16.row.col.f32.f16.f16.f32 "
                 "{%0,%1,%2,%3}, {%4,%5,%6,%7}, {%8,%9}, {%0,%1,%2,%3};"
                 : "+f"(d[0]), "+f"(d[1]), "+f"(d[2]), "+f"(d[3])
                 : "r"(a[0]), "r"(a[1]), "r"(a[2]), "r"(a[3]), "r"(b[0]), "r"(b[1]));
}
__device__ __forceinline__ uint32_t pack_h2(float a, float b) {
    __half2 h = __floats2half2_rn(a, b);
    return *(uint32_t*)&h;
}

// ---------------------------------------------------------------------------
// Fused prep kernel: x->fp16, 4 weights->fp16, RoPE table. One launch.
// ---------------------------------------------------------------------------
#define NBX ((B_*T_*C_) / 1024)     // 4096
#define NBW (CC_ / 1024)            // 1024
#define NBPREP (NBX + 4*NBW + 256)  // 8448

__global__ __launch_bounds__(256)
void prep_kernel(const float* __restrict__ x,
                 const float* __restrict__ Wq, const float* __restrict__ Wk,
                 const float* __restrict__ Wv, const float* __restrict__ Wo)
{
    int bid = blockIdx.x;
    if (bid < NBX + 4 * NBW) {
        const float* src;
        __half* dst;
        int lb;
        if (bid < NBX) {
            src = x; dst = g_xh; lb = bid;
        } else {
            int w = (bid - NBX) >> 10;          // which weight
            lb = (bid - NBX) & 1023;
            src = (w == 0) ? Wq : (w == 1) ? Wk : (w == 2) ? Wv : Wo;
            dst = g_wh + (size_t)w * CC_;
        }
        int i = (lb * 256 + threadIdx.x) * 4;
        float4 v = *(const float4*)(src + i);
        __half2 a = __floats2half2_rn(v.x, v.y);
        __half2 b = __floats2half2_rn(v.z, v.w);
        uint2 o;
        o.x = *(uint32_t*)&a;
        o.y = *(uint32_t*)&b;
        *(uint2*)(dst + i) = o;
    } else {
        int idx = (bid - NBX - 4 * NBW) * 256 + threadIdx.x;   // [0, 65536)
        int t = idx >> 5, d = idx & 31;
        float invf = exp2f(-0.4152410118609203f * (float)d);
        float sn, cs;
        sincosf((float)t * invf, &sn, &cs);
        g_rope[idx] = make_float2(cs, sn);
    }
}

// ---------------------------------------------------------------------------
// HMMA GEMM: Y = Xh @ W^T.  CTA 128x128, 4 warps (warp tile 64x64),
// BK=64, 2-stage cp.async pipeline (same bytes as old 3-stage BK=32),
// 128 threads, 2 CTAs/SM.  Barrier-free window: 32 ldsm + 128 MMAs.
// MODE 0: fp32 row-major Y (out-proj; W = Wbase).
// MODE 1: QKV fused: z = blockIdx.z selects W slice + destination;
//         z=0 -> RoPE+QSCALE -> g_qh, z=1 -> RoPE -> g_kh, z=2 -> g_vh (all fp16).
// ---------------------------------------------------------------------------
#define SSTR 72                         // smem row stride in halves (144B)
#define STG_HALVES (2 * 128 * SSTR)     // A(128 rows) + B(128 rows) per stage
#define GEMM_SMEM (2 * STG_HALVES * 2)  // 73728 B

template <int MODE>
__global__ __launch_bounds__(128, 2)
void gemm4(const __half* __restrict__ Xh, const __half* __restrict__ Wbase,
           float* __restrict__ Yout, int M, int N, int K)
{
    extern __shared__ __align__(16) __half sm[];

    const int tid  = threadIdx.x;
    const int wid  = tid >> 5;
    const int lane = tid & 31;
    const int m0 = blockIdx.y * 128;
    const int n0 = blockIdx.x * 128;
    const int wm = (wid & 1) * 64;
    const int wn = (wid >> 1) * 64;
    const int z  = (MODE == 1) ? blockIdx.z : 0;
    const __half* W = Wbase + (size_t)z * CC_;

    float acc[4][8][4];
#pragma unroll
    for (int i = 0; i < 4; i++)
#pragma unroll
        for (int j = 0; j < 8; j++)
#pragma unroll
            for (int c = 0; c < 4; c++) acc[i][j][c] = 0.f;

    // stage: 256 rows (A:128, B:128) x 64 halves = 2048 16B chunks, 16/thread
    auto issue_stage = [&](int s, int k0) {
        __half* St = sm + s * STG_HALVES;
#pragma unroll
        for (int li = 0; li < 16; li++) {
            int c   = tid + li * 128;
            int row = c >> 3;
            int seg = (c & 7) * 8;
            const __half* src = (row < 128)
                ? (Xh + (size_t)(m0 + row) * K + k0 + seg)
                : (W  + (size_t)(n0 + row - 128) * K + k0 + seg);
            cp_async16((uint32_t)__cvta_generic_to_shared(&St[row * SSTR + seg]), src);
        }
        asm volatile("cp.async.commit_group;");
    };

    const int NT = K / 64;   // 16
    issue_stage(0, 0);
    issue_stage(1, 64);

    for (int kt = 0; kt < NT; kt++) {
        const int s = kt & 1;
        if (kt + 1 < NT) asm volatile("cp.async.wait_group 1;");
        else             asm volatile("cp.async.wait_group 0;");
        __syncthreads();

        __half* As = sm + s * STG_HALVES;
        __half* Bs = As + 128 * SSTR;

#pragma unroll
        for (int kk = 0; kk < 4; kk++) {
            uint32_t af[4][4];
#pragma unroll
            for (int mi = 0; mi < 4; mi++) {
                uint32_t a = (uint32_t)__cvta_generic_to_shared(
                    &As[(wm + mi * 16 + (lane & 15)) * SSTR + kk * 16 + ((lane >> 4) << 3)]);
                ldmatrix_x4(af[mi][0], af[mi][1], af[mi][2], af[mi][3], a);
            }
            uint32_t bf[8][2];
#pragma unroll
            for (int nb = 0; nb < 4; nb++) {
                uint32_t r0, r1, r2, r3;
                uint32_t a = (uint32_t)__cvta_generic_to_shared(
                    &Bs[(wn + nb * 16 + (lane & 7) + ((lane >> 4) << 3)) * SSTR
                        + kk * 16 + ((lane >> 3) & 1) * 8]);
                ldmatrix_x4(r0, r1, r2, r3, a);
                bf[nb * 2 + 0][0] = r0; bf[nb * 2 + 0][1] = r1;
                bf[nb * 2 + 1][0] = r2; bf[nb * 2 + 1][1] = r3;
            }
#pragma unroll
            for (int mi = 0; mi < 4; mi++)
#pragma unroll
                for (int ni = 0; ni < 8; ni++)
                    mma16816(acc[mi][ni], af[mi], bf[ni]);
        }
        __syncthreads();
        if (kt + 2 < NT) issue_stage(s, (kt + 2) * 64);
    }

    // ---- epilogue ----
    if (MODE == 0) {
#pragma unroll
        for (int mi = 0; mi < 4; mi++)
#pragma unroll
            for (int h = 0; h < 2; h++) {
                int row = m0 + wm + mi * 16 + (lane >> 2) + h * 8;
#pragma unroll
                for (int ni = 0; ni < 8; ni++) {
                    int col = n0 + wn + ni * 8 + (lane & 3) * 2;
                    *(float2*)(Yout + (size_t)row * N + col) =
                        make_float2(acc[mi][ni][h * 2], acc[mi][ni][h * 2 + 1]);
                }
            }
    } else {
        const int hh = (n0 + wn) >> 6;       // one head per warp tile
#pragma unroll
        for (int mi = 0; mi < 4; mi++)
#pragma unroll
            for (int h = 0; h < 2; h++) {
                int row = m0 + wm + mi * 16 + (lane >> 2) + h * 8;
                int b = row >> 11;
                int t = row & (T_ - 1);
                size_t base = (((size_t)b * H_ + hh) * T_ + t) * D_;
                if (z == 2) {
#pragma unroll
                    for (int nj = 0; nj < 8; nj++) {
                        int d = nj * 8 + (lane & 3) * 2;
                        *(uint32_t*)(g_vh + base + d) =
                            pack_h2(acc[mi][nj][h * 2], acc[mi][nj][h * 2 + 1]);
                    }
                } else {
                    __half* dst = z ? g_kh : g_qh;
                    const float qs = z ? 1.f : QSCALE;
#pragma unroll
                    for (int nj = 0; nj < 4; nj++) {
                        float vlo[2], vhi[2];
#pragma unroll
                        for (int e = 0; e < 2; e++) {
                            int d = nj * 8 + (lane & 3) * 2 + e;     // [0,32)
                            float lo = acc[mi][nj][h * 2 + e];
                            float hi = acc[mi][nj + 4][h * 2 + e];
                            float2 cs = g_rope[t * 32 + d];
                            vlo[e] = (lo * cs.x - hi * cs.y) * qs;
                            vhi[e] = (hi * cs.x + lo * cs.y) * qs;
                        }
                        int d0 = nj * 8 + (lane & 3) * 2;
                        *(uint32_t*)(dst + base + d0)      = pack_h2(vlo[0], vlo[1]);
                        *(uint32_t*)(dst + base + d0 + 32) = pack_h2(vhi[0], vhi[1]);
                    }
                }
            }
    }
}

// ---------------------------------------------------------------------------
// Tensor-core causal flash attention (fp16 in, fp32 accum), writes fp16 [B,T,C].
// CTA: 128 q-rows, 4 warps, KV tiles of 64.  grid (B*H, T/128), 128 threads.
// Heavy q-tiles scheduled first; 3-stage K/V ring, ONE barrier per tile.
// ---------------------------------------------------------------------------
#define ATS 72   // 144B stride: 16B-aligned, ldmatrix rows hit disjoint bank quads

__global__ __launch_bounds__(128)
void attn_mma()
{
    extern __shared__ __half ash[];
    __half (*Qs)[ATS] = (__half(*)[ATS])ash;
    __half (*Ks)[64][ATS] = (__half(*)[64][ATS])(ash + 128 * ATS);           // [3]
    __half (*Vs)[64][ATS] = (__half(*)[64][ATS])(ash + (128 + 3*64) * ATS);  // [3]

    const int bh = blockIdx.x;
    const int qt = (gridDim.y - 1) - blockIdx.y;   // heavy tiles first
    const int tid = threadIdx.x, wid = tid >> 5, lane = tid & 31;

    const __half* Qg = g_qh + ((size_t)bh * T_ + qt * 128) * D_;
    const __half* Kg = g_kh + (size_t)bh * T_ * D_;
    const __half* Vg = g_vh + (size_t)bh * T_ * D_;

#pragma unroll
    for (int i = 0; i < 8; i++) {
        int c = tid + i * 128;
        int row = c >> 3, seg = c & 7;
        *(uint4*)&Qs[row][seg * 8] = *(const uint4*)(Qg + row * 64 + seg * 8);
    }
    __syncthreads();

    uint32_t qa[2][4][4];
#pragma unroll
    for (int mi = 0; mi < 2; mi++)
#pragma unroll
        for (int t = 0; t < 4; t++) {
            uint32_t a = (uint32_t)__cvta_generic_to_shared(
                &Qs[wid * 32 + mi * 16 + ((lane >> 3) & 1) * 8 + (lane & 7)]
                   [t * 16 + (lane >> 4) * 8]);
            ldmatrix_x4(qa[mi][t][0], qa[mi][t][1], qa[mi][t][2], qa[mi][t][3], a);
        }

    float O[2][8][4];
#pragma unroll
    for (int mi = 0; mi < 2; mi++)
#pragma unroll
        for (int nj = 0; nj < 8; nj++)
#pragma unroll
            for (int c = 0; c < 4; c++) O[mi][nj][c] = 0.f;
    float mrow[2][2] = {{-INFINITY, -INFINITY}, {-INFINITY, -INFINITY}};
    float lrow[2][2] = {{0.f, 0.f}, {0.f, 0.f}};

    const int nkt = 2 * qt + 2;

    auto issue = [&](int s, int kt) {
#pragma unroll
        for (int i = 0; i < 8; i++) {
            int c = tid + i * 128;
            int isV = c >> 9, cc = c & 511, row = cc >> 3, seg = cc & 7;
            const __half* src = (isV ? Vg : Kg) + (size_t)(kt * 64 + row) * 64 + seg * 8;
            uint32_t dst = (uint32_t)__cvta_generic_to_shared(
                isV ? &Vs[s][row][seg * 8] : &Ks[s][row][seg * 8]);
            cp_async16(dst, src);
        }
        asm volatile("cp.async.commit_group;");
    };
    issue(0, 0);

    for (int kt = 0; kt < nkt; kt++) {
        const int s = kt % 3;
        if (kt + 1 < nkt) {
            issue((kt + 1) % 3, kt + 1);
            asm volatile("cp.async.wait_group 1;");
        } else {
            asm volatile("cp.async.wait_group 0;");
        }
        __syncthreads();   // single barrier per tile

        bool active = (qt * 128 + wid * 32 + 31) >= kt * 64;
        if (active) {
            float S[2][8][4];
#pragma unroll
            for (int mi = 0; mi < 2; mi++)
#pragma unroll
                for (int nj = 0; nj < 8; nj++)
#pragma unroll
                    for (int c = 0; c < 4; c++) S[mi][nj][c] = 0.f;

#pragma unroll
            for (int t = 0; t < 4; t++) {
                uint32_t bf[8][2];
#pragma unroll
                for (int jp = 0; jp < 4; jp++) {
                    uint32_t a = (uint32_t)__cvta_generic_to_shared(
                        &Ks[s][jp * 16 + ((lane >> 4) & 1) * 8 + (lane & 7)]
                            [t * 16 + ((lane >> 3) & 1) * 8]);
                    ldmatrix_x4(bf[2*jp][0], bf[2*jp][1], bf[2*jp+1][0], bf[2*jp+1][1], a);
                }
#pragma unroll
                for (int mi = 0; mi < 2; mi++)
#pragma unroll
                    for (int nj = 0; nj < 8; nj++)
                        mma16816(S[mi][nj], qa[mi][t], bf[nj]);
            }

            if (kt >= 2 * qt) {
#pragma unroll
                for (int mi = 0; mi < 2; mi++)
#pragma unroll
                    for (int h = 0; h < 2; h++) {
                        int row = qt * 128 + wid * 32 + mi * 16 + (lane >> 2) + h * 8;
#pragma unroll
                        for (int nj = 0; nj < 8; nj++)
#pragma unroll
                            for (int e = 0; e < 2; e++) {
                                int key = kt * 64 + nj * 8 + (lane & 3) * 2 + e;
                                if (key > row) S[mi][nj][h * 2 + e] = -1e30f;
                            }
                    }
            }

            float al[2][2];
#pragma unroll
            for (int mi = 0; mi < 2; mi++)
#pragma unroll
                for (int h = 0; h < 2; h++) {
                    float rm = -1e30f;
#pragma unroll
                    for (int nj = 0; nj < 8; nj++)
                        rm = fmaxf(rm, fmaxf(S[mi][nj][h*2], S[mi][nj][h*2+1]));
                    rm = fmaxf(rm, __shfl_xor_sync(0xffffffffu, rm, 1));
                    rm = fmaxf(rm, __shfl_xor_sync(0xffffffffu, rm, 2));
                    float mn = fmaxf(mrow[mi][h], rm);
                    float alpha = exp2f(mrow[mi][h] - mn);
                    mrow[mi][h] = mn;
                    float ps = 0.f;
#pragma unroll
                    for (int nj = 0; nj < 8; nj++) {
                        float p0 = exp2f(S[mi][nj][h*2]   - mn);
                        float p1 = exp2f(S[mi][nj][h*2+1] - mn);
                        S[mi][nj][h*2]   = p0;
                        S[mi][nj][h*2+1] = p1;
                        ps += p0 + p1;
                    }
                    ps += __shfl_xor_sync(0xffffffffu, ps, 1);
                    ps += __shfl_xor_sync(0xffffffffu, ps, 2);
                    lrow[mi][h] = lrow[mi][h] * alpha + ps;
                    al[mi][h] = alpha;
                }
#pragma unroll
            for (int mi = 0; mi < 2; mi++)
#pragma unroll
                for (int nj = 0; nj < 8; nj++) {
                    O[mi][nj][0] *= al[mi][0];
                    O[mi][nj][1] *= al[mi][0];
                    O[mi][nj][2] *= al[mi][1];
                    O[mi][nj][3] *= al[mi][1];
                }

#pragma unroll
            for (int t = 0; t < 4; t++) {
                uint32_t bv[8][2];
#pragma unroll
                for (int jp = 0; jp < 4; jp++) {
                    uint32_t a = (uint32_t)__cvta_generic_to_shared(
                        &Vs[s][t * 16 + ((lane >> 3) & 1) * 8 + (lane & 7)]
                            [(2 * jp + ((lane >> 4) & 1)) * 8]);
                    ldmatrix_x4_t(bv[2*jp][0], bv[2*jp][1], bv[2*jp+1][0], bv[2*jp+1][1], a);
                }
#pragma unroll
                for (int mi = 0; mi < 2; mi++) {
                    uint32_t pa[4];
                    pa[0] = pack_h2(S[mi][2*t][0],   S[mi][2*t][1]);
                    pa[1] = pack_h2(S[mi][2*t][2],   S[mi][2*t][3]);
                    pa[2] = pack_h2(S[mi][2*t+1][0], S[mi][2*t+1][1]);
                    pa[3] = pack_h2(S[mi][2*t+1][2], S[mi][2*t+1][3]);
#pragma unroll
                    for (int nj = 0; nj < 8; nj++)
                        mma16816(O[mi][nj], pa, bv[nj]);
                }
            }
        }
    }

    // epilogue: normalize, write fp16 into g_xh [B,T,C]
    const int b = bh >> 4, hh = bh & (H_ - 1);
#pragma unroll
    for (int mi = 0; mi < 2; mi++)
#pragma unroll
        for (int h = 0; h < 2; h++) {
            float inv = 1.f / lrow[mi][h];
            int row = qt * 128 + wid * 32 + mi * 16 + (lane >> 2) + h * 8;
            __half* dst = g_xh + ((size_t)(b * T_ + row)) * C_ + hh * 64;
#pragma unroll
            for (int nj = 0; nj < 8; nj++)
                *(uint32_t*)(dst + nj * 8 + (lane & 3) * 2) =
                    pack_h2(O[mi][nj][h*2] * inv, O[mi][nj][h*2+1] * inv);
        }
}

// ---------------------------------------------------------------------------
extern "C" void kernel_launch(void* const* d_in, const int* in_sizes, int n_in,
                              void* d_out, int out_size)
{
    const float* x  = (const float*)d_in[0];
    const float* Wq = (const float*)d_in[1];
    const float* Wk = (const float*)d_in[2];
    const float* Wv = (const float*)d_in[3];
    const float* Wo = (const float*)d_in[4];
    float* out = (float*)d_out;

    __half *xh, *wh;
    cudaGetSymbolAddress((void**)&xh, g_xh);
    cudaGetSymbolAddress((void**)&wh, g_wh);

    const int M = B_ * T_;   // 4096

    cudaFuncSetAttribute(gemm4<0>, cudaFuncAttributeMaxDynamicSharedMemorySize, GEMM_SMEM);
    cudaFuncSetAttribute(gemm4<1>, cudaFuncAttributeMaxDynamicSharedMemorySize, GEMM_SMEM);

    prep_kernel<<<NBPREP, 256>>>(x, Wq, Wk, Wv, Wo);

    gemm4<1><<<dim3(C_ / 128, M / 128, 3), 128, GEMM_SMEM>>>(xh, wh, nullptr, M, C_, C_);

    int asmem = (128 + 3 * 64 + 3 * 64) * ATS * 2;   // 73728 B
    cudaFuncSetAttribute(attn_mma, cudaFuncAttributeMaxDynamicSharedMemorySize, asmem);
    attn_mma<<<dim3(B_ * H_, T_ / 128), 128, asmem>>>();

    gemm4<0><<<dim3(C_ / 128, M / 128), 128, GEMM_SMEM>>>(xh, wh + 3 * CC_, out, M, C_, C_);
}

// round 16
// speedup vs baseline: 1.0454x; 1.0454x over previous
#include <cuda_runtime.h>
#include <cuda_fp16.h>
#include <math.h>
#include <stdint.h>

#define B_ 2
#define T_ 2048
#define C_ 1024
#define H_ 16
#define D_ 64
#define CC_ (C_*C_)

// Scratch (allocation-free rule: __device__ globals)
__device__ __half g_xh[(size_t)B_*T_*C_];      // fp16 activations (x, then attn out)
__device__ __half g_wh[(size_t)4*CC_];         // fp16 weights: Wq,Wk,Wv,Wo
__device__ __half g_qh[(size_t)B_*H_*T_*D_];
__device__ __half g_kh[(size_t)B_*H_*T_*D_];
__device__ __half g_vh[(size_t)B_*H_*T_*D_];
__device__ float2 g_rope[(size_t)T_*32];       // (cos, sin) per (t, d)

#define QSCALE 0.18033688011112042f   // 0.125 * log2(e)

// ---------------------------------------------------------------------------
// common helpers
// ---------------------------------------------------------------------------
__device__ __forceinline__ void cp_async16(uint32_t dst, const void* src) {
    asm volatile("cp.async.ca.shared.global [%0], [%1], 16;" :: "r"(dst), "l"(src));
}
__device__ __forceinline__ void ldmatrix_x4(uint32_t& r0, uint32_t& r1,
                                            uint32_t& r2, uint32_t& r3, uint32_t a) {
    asm volatile("ldmatrix.sync.aligned.m8n8.x4.shared.b16 {%0,%1,%2,%3}, [%4];"
                 : "=r"(r0), "=r"(r1), "=r"(r2), "=r"(r3) : "r"(a));
}
__device__ __forceinline__ void ldmatrix_x4_t(uint32_t& r0, uint32_t& r1,
                                              uint32_t& r2, uint32_t& r3, uint32_t a) {
    asm volatile("ldmatrix.sync.aligned.m8n8.x4.trans.shared.b16 {%0,%1,%2,%3}, [%4];"
                 : "=r"(r0), "=r"(r1), "=r"(r2), "=r"(r3) : "r"(a));
}
__device__ __forceinline__ void mma16816(float* d, const uint32_t* a, const uint32_t* b) {
    asm volatile("mma.sync.aligned.m16n8k16.row.col.f32.f16.f16.f32 "
                 "{%0,%1,%2,%3}, {%4,%5,%6,%7}, {%8,%9}, {%0,%1,%2,%3};"
                 : "+f"(d[0]), "+f"(d[1]), "+f"(d[2]), "+f"(d[3])
                 : "r"(a[0]), "r"(a[1]), "r"(a[2]), "r"(a[3]), "r"(b[0]), "r"(b[1]));
}
__device__ __forceinline__ uint32_t pack_h2(float a, float b) {
    __half2 h = __floats2half2_rn(a, b);
    return *(uint32_t*)&h;
}

// ---------------------------------------------------------------------------
// Fused prep kernel: x->fp16, 4 weights->fp16, RoPE table. One launch.
// Convert blocks process 4096 floats each (16 per thread, 4x float4,
// block-strided so each inner step touches one contiguous 4KB span).
// ---------------------------------------------------------------------------
#define NBX ((B_*T_*C_) / 4096)     // 2048
#define NBW (CC_ / 4096)            // 256
#define NBPREP (NBX + 4*NBW + 256)  // 3328

__global__ __launch_bounds__(256)
void prep_kernel(const float* __restrict__ x,
                 const float* __restrict__ Wq, const float* __restrict__ Wk,
                 const float* __restrict__ Wv, const float* __restrict__ Wo)
{
    int bid = blockIdx.x;
    if (bid < NBX + 4 * NBW) {
        const float* src;
        __half* dst;
        int lb;
        if (bid < NBX) {
            src = x; dst = g_xh; lb = bid;
        } else {
            int w = (bid - NBX) >> 8;           // which weight
            lb = (bid - NBX) & 255;
            src = (w == 0) ? Wq : (w == 1) ? Wk : (w == 2) ? Wv : Wo;
            dst = g_wh + (size_t)w * CC_;
        }
#pragma unroll
        for (int j = 0; j < 4; j++) {
            int i = lb * 4096 + j * 1024 + threadIdx.x * 4;
            float4 v = *(const float4*)(src + i);
            __half2 a = __floats2half2_rn(v.x, v.y);
            __half2 b = __floats2half2_rn(v.z, v.w);
            uint2 o;
            o.x = *(uint32_t*)&a;
            o.y = *(uint32_t*)&b;
            *(uint2*)(dst + i) = o;
        }
    } else {
        int idx = (bid - NBX - 4 * NBW) * 256 + threadIdx.x;   // [0, 65536)
        int t = idx >> 5, d = idx & 31;
        float invf = exp2f(-0.4152410118609203f * (float)d);
        float sn, cs;
        sincosf((float)t * invf, &sn, &cs);
        g_rope[idx] = make_float2(cs, sn);
    }
}

// ---------------------------------------------------------------------------
// HMMA GEMM (round-12 champion config): Y = Xh @ W^T.  CTA 128x128, 4 warps
// (warp tile 64x64), BK=32, 3-stage cp.async pipeline, 128 threads, 2 CTAs/SM.
// MODE 0: fp32 row-major Y (out-proj; W = Wbase).
// MODE 1: QKV fused: z = blockIdx.z selects W slice + destination;
//         z=0 -> RoPE+QSCALE -> g_qh, z=1 -> RoPE -> g_kh, z=2 -> g_vh (all fp16).
// ---------------------------------------------------------------------------
#define SSTR 40                         // smem row stride in halves
#define STG_HALVES (2 * 128 * SSTR)     // A + B per stage
#define GEMM_SMEM (3 * STG_HALVES * 2)  // 61440 B

template <int MODE>
__global__ __launch_bounds__(128, 2)
void gemm4(const __half* __restrict__ Xh, const __half* __restrict__ Wbase,
           float* __restrict__ Yout, int M, int N, int K)
{
    extern __shared__ __align__(16) __half sm[];

    const int tid  = threadIdx.x;
    const int wid  = tid >> 5;
    const int lane = tid & 31;
    const int m0 = blockIdx.y * 128;
    const int n0 = blockIdx.x * 128;
    const int wm = (wid & 1) * 64;
    const int wn = (wid >> 1) * 64;
    const int z  = (MODE == 1) ? blockIdx.z : 0;
    const __half* W = Wbase + (size_t)z * CC_;

    float acc[4][8][4];
#pragma unroll
    for (int i = 0; i < 4; i++)
#pragma unroll
        for (int j = 0; j < 8; j++)
#pragma unroll
            for (int c = 0; c < 4; c++) acc[i][j][c] = 0.f;

    auto issue_stage = [&](int s, int k0) {
        __half* As = sm + s * STG_HALVES;
        __half* Bs = As + 128 * SSTR;
#pragma unroll
        for (int li = 0; li < 4; li++) {
            int c   = tid + li * 128;
            int row = c >> 2;
            int seg = (c & 3) * 8;
            cp_async16((uint32_t)__cvta_generic_to_shared(&As[row * SSTR + seg]),
                       Xh + (size_t)(m0 + row) * K + k0 + seg);
            cp_async16((uint32_t)__cvta_generic_to_shared(&Bs[row * SSTR + seg]),
                       W + (size_t)(n0 + row) * K + k0 + seg);
        }
        asm volatile("cp.async.commit_group;");
    };

    const int NT = K / 32;
    issue_stage(0, 0);
    issue_stage(1, 32);

    for (int kt = 0; kt < NT; kt++) {
        const int s = kt % 3;
        if (kt + 1 < NT) asm volatile("cp.async.wait_group 1;");
        else             asm volatile("cp.async.wait_group 0;");
        __syncthreads();

        __half* As = sm + s * STG_HALVES;
        __half* Bs = As + 128 * SSTR;

#pragma unroll
        for (int kk = 0; kk < 2; kk++) {
            uint32_t af[4][4];
#pragma unroll
            for (int mi = 0; mi < 4; mi++) {
                uint32_t a = (uint32_t)__cvta_generic_to_shared(
                    &As[(wm + mi * 16 + (lane & 15)) * SSTR + kk * 16 + ((lane >> 4) << 3)]);
                ldmatrix_x4(af[mi][0], af[mi][1], af[mi][2], af[mi][3], a);
            }
            uint32_t bf[8][2];
#pragma unroll
            for (int nb = 0; nb < 4; nb++) {
                uint32_t r0, r1, r2, r3;
                uint32_t a = (uint32_t)__cvta_generic_to_shared(
                    &Bs[(wn + nb * 16 + (lane & 7) + ((lane >> 4) << 3)) * SSTR
                        + kk * 16 + ((lane >> 3) & 1) * 8]);
                ldmatrix_x4(r0, r1, r2, r3, a);
                bf[nb * 2 + 0][0] = r0; bf[nb * 2 + 0][1] = r1;
                bf[nb * 2 + 1][0] = r2; bf[nb * 2 + 1][1] = r3;
            }
#pragma unroll
            for (int mi = 0; mi < 4; mi++)
#pragma unroll
                for (int ni = 0; ni < 8; ni++)
                    mma16816(acc[mi][ni], af[mi], bf[ni]);
        }
        __syncthreads();
        if (kt + 2 < NT) issue_stage((kt + 2) % 3, (kt + 2) * 32);
    }

    // ---- epilogue ----
    if (MODE == 0) {
#pragma unroll
        for (int mi = 0; mi < 4; mi++)
#pragma unroll
            for (int h = 0; h < 2; h++) {
                int row = m0 + wm + mi * 16 + (lane >> 2) + h * 8;
#pragma unroll
                for (int ni = 0; ni < 8; ni++) {
                    int col = n0 + wn + ni * 8 + (lane & 3) * 2;
                    *(float2*)(Yout + (size_t)row * N + col) =
                        make_float2(acc[mi][ni][h * 2], acc[mi][ni][h * 2 + 1]);
                }
            }
    } else {
        const int hh = (n0 + wn) >> 6;       // one head per warp tile
#pragma unroll
        for (int mi = 0; mi < 4; mi++)
#pragma unroll
            for (int h = 0; h < 2; h++) {
                int row = m0 + wm + mi * 16 + (lane >> 2) + h * 8;
                int b = row >> 11;
                int t = row & (T_ - 1);
                size_t base = (((size_t)b * H_ + hh) * T_ + t) * D_;
                if (z == 2) {
#pragma unroll
                    for (int nj = 0; nj < 8; nj++) {
                        int d = nj * 8 + (lane & 3) * 2;
                        *(uint32_t*)(g_vh + base + d) =
                            pack_h2(acc[mi][nj][h * 2], acc[mi][nj][h * 2 + 1]);
                    }
                } else {
                    __half* dst = z ? g_kh : g_qh;
                    const float qs = z ? 1.f : QSCALE;
#pragma unroll
                    for (int nj = 0; nj < 4; nj++) {
                        float vlo[2], vhi[2];
#pragma unroll
                        for (int e = 0; e < 2; e++) {
                            int d = nj * 8 + (lane & 3) * 2 + e;     // [0,32)
                            float lo = acc[mi][nj][h * 2 + e];
                            float hi = acc[mi][nj + 4][h * 2 + e];
                            float2 cs = g_rope[t * 32 + d];
                            vlo[e] = (lo * cs.x - hi * cs.y) * qs;
                            vhi[e] = (hi * cs.x + lo * cs.y) * qs;
                        }
                        int d0 = nj * 8 + (lane & 3) * 2;
                        *(uint32_t*)(dst + base + d0)      = pack_h2(vlo[0], vlo[1]);
                        *(uint32_t*)(dst + base + d0 + 32) = pack_h2(vhi[0], vhi[1]);
                    }
                }
            }
    }
}

// ---------------------------------------------------------------------------
// Tensor-core causal flash attention (fp16 in, fp32 accum), writes fp16 [B,T,C].
// CTA: 128 q-rows, 4 warps, KV tiles of 64.  grid (B*H, T/128), 128 threads.
// Heavy q-tiles scheduled first; 3-stage K/V ring, ONE barrier per tile.
// ---------------------------------------------------------------------------
#define ATS 72   // 144B stride: 16B-aligned, ldmatrix rows hit disjoint bank quads

__global__ __launch_bounds__(128)
void attn_mma()
{
    extern __shared__ __half ash[];
    __half (*Qs)[ATS] = (__half(*)[ATS])ash;
    __half (*Ks)[64][ATS] = (__half(*)[64][ATS])(ash + 128 * ATS);           // [3]
    __half (*Vs)[64][ATS] = (__half(*)[64][ATS])(ash + (128 + 3*64) * ATS);  // [3]

    const int bh = blockIdx.x;
    const int qt = (gridDim.y - 1) - blockIdx.y;   // heavy tiles first
    const int tid = threadIdx.x, wid = tid >> 5, lane = tid & 31;

    const __half* Qg = g_qh + ((size_t)bh * T_ + qt * 128) * D_;
    const __half* Kg = g_kh + (size_t)bh * T_ * D_;
    const __half* Vg = g_vh + (size_t)bh * T_ * D_;

#pragma unroll
    for (int i = 0; i < 8; i++) {
        int c = tid + i * 128;
        int row = c >> 3, seg = c & 7;
        *(uint4*)&Qs[row][seg * 8] = *(const uint4*)(Qg + row * 64 + seg * 8);
    }
    __syncthreads();

    uint32_t qa[2][4][4];
#pragma unroll
    for (int mi = 0; mi < 2; mi++)
#pragma unroll
        for (int t = 0; t < 4; t++) {
            uint32_t a = (uint32_t)__cvta_generic_to_shared(
                &Qs[wid * 32 + mi * 16 + ((lane >> 3) & 1) * 8 + (lane & 7)]
                   [t * 16 + (lane >> 4) * 8]);
            ldmatrix_x4(qa[mi][t][0], qa[mi][t][1], qa[mi][t][2], qa[mi][t][3], a);
        }

    float O[2][8][4];
#pragma unroll
    for (int mi = 0; mi < 2; mi++)
#pragma unroll
        for (int nj = 0; nj < 8; nj++)
#pragma unroll
            for (int c = 0; c < 4; c++) O[mi][nj][c] = 0.f;
    float mrow[2][2] = {{-INFINITY, -INFINITY}, {-INFINITY, -INFINITY}};
    float lrow[2][2] = {{0.f, 0.f}, {0.f, 0.f}};

    const int nkt = 2 * qt + 2;

    auto issue = [&](int s, int kt) {
#pragma unroll
        for (int i = 0; i < 8; i++) {
            int c = tid + i * 128;
            int isV = c >> 9, cc = c & 511, row = cc >> 3, seg = cc & 7;
            const __half* src = (isV ? Vg : Kg) + (size_t)(kt * 64 + row) * 64 + seg * 8;
            uint32_t dst = (uint32_t)__cvta_generic_to_shared(
                isV ? &Vs[s][row][seg * 8] : &Ks[s][row][seg * 8]);
            cp_async16(dst, src);
        }
        asm volatile("cp.async.commit_group;");
    };
    issue(0, 0);

    for (int kt = 0; kt < nkt; kt++) {
        const int s = kt % 3;
        if (kt + 1 < nkt) {
            issue((kt + 1) % 3, kt + 1);
            asm volatile("cp.async.wait_group 1;");
        } else {
            asm volatile("cp.async.wait_group 0;");
        }
        __syncthreads();   // single barrier per tile

        bool active = (qt * 128 + wid * 32 + 31) >= kt * 64;
        if (active) {
            float S[2][8][4];
#pragma unroll
            for (int mi = 0; mi < 2; mi++)
#pragma unroll
                for (int nj = 0; nj < 8; nj++)
#pragma unroll
                    for (int c = 0; c < 4; c++) S[mi][nj][c] = 0.f;

#pragma unroll
            for (int t = 0; t < 4; t++) {
                uint32_t bf[8][2];
#pragma unroll
                for (int jp = 0; jp < 4; jp++) {
                    uint32_t a = (uint32_t)__cvta_generic_to_shared(
                        &Ks[s][jp * 16 + ((lane >> 4) & 1) * 8 + (lane & 7)]
                            [t * 16 + ((lane >> 3) & 1) * 8]);
                    ldmatrix_x4(bf[2*jp][0], bf[2*jp][1], bf[2*jp+1][0], bf[2*jp+1][1], a);
                }
#pragma unroll
                for (int mi = 0; mi < 2; mi++)
#pragma unroll
                    for (int nj = 0; nj < 8; nj++)
                        mma16816(S[mi][nj], qa[mi][t], bf[nj]);
            }

            if (kt >= 2 * qt) {
#pragma unroll
                for (int mi = 0; mi < 2; mi++)
#pragma unroll
                    for (int h = 0; h < 2; h++) {
                        int row = qt * 128 + wid * 32 + mi * 16 + (lane >> 2) + h * 8;
#pragma unroll
                        for (int nj = 0; nj < 8; nj++)
#pragma unroll
                            for (int e = 0; e < 2; e++) {
                                int key = kt * 64 + nj * 8 + (lane & 3) * 2 + e;
                                if (key > row) S[mi][nj][h * 2 + e] = -1e30f;
                            }
                    }
            }

            float al[2][2];
#pragma unroll
            for (int mi = 0; mi < 2; mi++)
#pragma unroll
                for (int h = 0; h < 2; h++) {
                    float rm = -1e30f;
#pragma unroll
                    for (int nj = 0; nj < 8; nj++)
                        rm = fmaxf(rm, fmaxf(S[mi][nj][h*2], S[mi][nj][h*2+1]));
                    rm = fmaxf(rm, __shfl_xor_sync(0xffffffffu, rm, 1));
                    rm = fmaxf(rm, __shfl_xor_sync(0xffffffffu, rm, 2));
                    float mn = fmaxf(mrow[mi][h], rm);
                    float alpha = exp2f(mrow[mi][h] - mn);
                    mrow[mi][h] = mn;
                    float ps = 0.f;
#pragma unroll
                    for (int nj = 0; nj < 8; nj++) {
                        float p0 = exp2f(S[mi][nj][h*2]   - mn);
                        float p1 = exp2f(S[mi][nj][h*2+1] - mn);
                        S[mi][nj][h*2]   = p0;
                        S[mi][nj][h*2+1] = p1;
                        ps += p0 + p1;
                    }
                    ps += __shfl_xor_sync(0xffffffffu, ps, 1);
                    ps += __shfl_xor_sync(0xffffffffu, ps, 2);
                    lrow[mi][h] = lrow[mi][h] * alpha + ps;
                    al[mi][h] = alpha;
                }
#pragma unroll
            for (int mi = 0; mi < 2; mi++)
#pragma unroll
                for (int nj = 0; nj < 8; nj++) {
                    O[mi][nj][0] *= al[mi][0];
                    O[mi][nj][1] *= al[mi][0];
                    O[mi][nj][2] *= al[mi][1];
                    O[mi][nj][3] *= al[mi][1];
                }

#pragma unroll
            for (int t = 0; t < 4; t++) {
                uint32_t bv[8][2];
#pragma unroll
                for (int jp = 0; jp < 4; jp++) {
                    uint32_t a = (uint32_t)__cvta_generic_to_shared(
                        &Vs[s][t * 16 + ((lane >> 3) & 1) * 8 + (lane & 7)]
                            [(2 * jp + ((lane >> 4) & 1)) * 8]);
                    ldmatrix_x4_t(bv[2*jp][0], bv[2*jp][1], bv[2*jp+1][0], bv[2*jp+1][1], a);
                }
#pragma unroll
                for (int mi = 0; mi < 2; mi++) {
                    uint32_t pa[4];
                    pa[0] = pack_h2(S[mi][2*t][0],   S[mi][2*t][1]);
                    pa[1] = pack_h2(S[mi][2*t][2],   S[mi][2*t][3]);
                    pa[2] = pack_h2(S[mi][2*t+1][0], S[mi][2*t+1][1]);
                    pa[3] = pack_h2(S[mi][2*t+1][2], S[mi][2*t+1][3]);
#pragma unroll
                    for (int nj = 0; nj < 8; nj++)
                        mma16816(O[mi][nj], pa, bv[nj]);
                }
            }
        }
    }

    // epilogue: normalize, write fp16 into g_xh [B,T,C]
    const int b = bh >> 4, hh = bh & (H_ - 1);
#pragma unroll
    for (int mi = 0; mi < 2; mi++)
#pragma unroll
        for (int h = 0; h < 2; h++) {
            float inv = 1.f / lrow[mi][h];
            int row = qt * 128 + wid * 32 + mi * 16 + (lane >> 2) + h * 8;
            __half* dst = g_xh + ((size_t)(b * T_ + row)) * C_ + hh * 64;
#pragma unroll
            for (int nj = 0; nj < 8; nj++)
                *(uint32_t*)(dst + nj * 8 + (lane & 3) * 2) =
                    pack_h2(O[mi][nj][h*2] * inv, O[mi][nj][h*2+1] * inv);
        }
}

// ---------------------------------------------------------------------------
extern "C" void kernel_launch(void* const* d_in, const int* in_sizes, int n_in,
                              void* d_out, int out_size)
{
    const float* x  = (const float*)d_in[0];
    const float* Wq = (const float*)d_in[1];
    const float* Wk = (const float*)d_in[2];
    const float* Wv = (const float*)d_in[3];
    const float* Wo = (const float*)d_in[4];
    float* out = (float*)d_out;

    __half *xh, *wh;
    cudaGetSymbolAddress((void**)&xh, g_xh);
    cudaGetSymbolAddress((void**)&wh, g_wh);

    const int M = B_ * T_;   // 4096

    cudaFuncSetAttribute(gemm4<0>, cudaFuncAttributeMaxDynamicSharedMemorySize, GEMM_SMEM);
    cudaFuncSetAttribute(gemm4<1>, cudaFuncAttributeMaxDynamicSharedMemorySize, GEMM_SMEM);

    prep_kernel<<<NBPREP, 256>>>(x, Wq, Wk, Wv, Wo);

    gemm4<1><<<dim3(C_ / 128, M / 128, 3), 128, GEMM_SMEM>>>(xh, wh, nullptr, M, C_, C_);

    int asmem = (128 + 3 * 64 + 3 * 64) * ATS * 2;   // 73728 B
    cudaFuncSetAttribute(attn_mma, cudaFuncAttributeMaxDynamicSharedMemorySize, asmem);
    attn_mma<<<dim3(B_ * H_, T_ / 128), 128, asmem>>>();

    gemm4<0><<<dim3(C_ / 128, M / 128), 128, GEMM_SMEM>>>(xh, wh + 3 * CC_, out, M, C_, C_);
}